// round 1
// baseline (speedup 1.0000x reference)
#include <cuda_runtime.h>
#include <math.h>

// ---------------- problem constants ----------------
#define Bb   4
#define Nn   1024
#define Dd   1024
#define Hh   16
#define DH   64
#define MLPd 4096

#define BN_TOK (Bb*Nn)        // 4096 rows
#define MAT    (Bb*Nn*Dd)     // 4M elems, 16MB

// ---------------- device scratch (no cudaMalloc allowed) ----------------
__device__ float g_q [MAT];              // q / qc / h2
__device__ float g_k [MAT];              // k / kc
__device__ float g_v [MAT];              // v / vc
__device__ float g_s [MAT];              // sa dots+attn / ca out
__device__ float g_sa[MAT];              // sa (post-LN) / ca (post-LN)
__device__ float g_t [Bb*Hh*Nn*DH];      // T = qc@kc  (4M elems)
__device__ float g_dca[(long)Bb*Hh*Nn*Nn]; // ca dots/attn (64M elems, 256MB)
__device__ float g_ff[(long)BN_TOK*MLPd];  // FF hidden (16M elems, 64MB)

// ---------------- generic tiled SGEMM ----------------
// C = alpha * A * B      (TRB=false)   A:[M,K] lda, B:[K,N] ldb
// C = alpha * A * B^T    (TRB=true )   A:[M,K] lda, B:[N,K] ldb
// batch via blockIdx.z: z = zb*bdiv + zh, offsets zb*s?b + zh*s?h
template<int BM, int BN, int BK, int TM, int TN, bool TRB>
__global__ void __launch_bounds__((BM/TM)*(BN/TN))
gemm_kernel(const float* __restrict__ A, const float* __restrict__ B,
            float* __restrict__ C,
            int K, int lda, int ldb, int ldc,
            int bdiv,
            long sAb, long sAh, long sBb, long sBh, long sCb, long sCh,
            float alpha)
{
    constexpr int THREADS = (BM/TM)*(BN/TN);
    __shared__ float As[BK][BM];
    __shared__ float Bs[BK][BN];

    int z  = blockIdx.z;
    int zb = z / bdiv, zh = z % bdiv;
    A += zb * sAb + zh * sAh;
    B += zb * sBb + zh * sBh;
    C += zb * sCb + zh * sCh;

    const int tid = threadIdx.x;
    const int tx  = tid % (BN/TN);
    const int ty  = tid / (BN/TN);
    const int rowBase = blockIdx.y * BM;
    const int colBase = blockIdx.x * BN;

    float acc[TM][TN];
    #pragma unroll
    for (int i = 0; i < TM; i++)
        #pragma unroll
        for (int j = 0; j < TN; j++) acc[i][j] = 0.0f;

    for (int k0 = 0; k0 < K; k0 += BK) {
        // load A tile (BM x BK), store transposed
        #pragma unroll
        for (int idx = tid; idx < BM*BK; idx += THREADS) {
            int r = idx / BK, c = idx % BK;
            As[c][r] = A[(long)(rowBase + r) * lda + (k0 + c)];
        }
        // load B tile
        if (!TRB) {
            #pragma unroll
            for (int idx = tid; idx < BK*BN; idx += THREADS) {
                int r = idx / BN, c = idx % BN;
                Bs[r][c] = B[(long)(k0 + r) * ldb + (colBase + c)];
            }
        } else {
            #pragma unroll
            for (int idx = tid; idx < BN*BK; idx += THREADS) {
                int r = idx / BK, c = idx % BK;   // r over N, c over K
                Bs[c][r] = B[(long)(colBase + r) * ldb + (k0 + c)];
            }
        }
        __syncthreads();

        #pragma unroll
        for (int kk = 0; kk < BK; kk++) {
            float ar[TM], br[TN];
            #pragma unroll
            for (int i = 0; i < TM; i++) ar[i] = As[kk][ty*TM + i];
            #pragma unroll
            for (int j = 0; j < TN; j++) br[j] = Bs[kk][tx*TN + j];
            #pragma unroll
            for (int i = 0; i < TM; i++)
                #pragma unroll
                for (int j = 0; j < TN; j++)
                    acc[i][j] += ar[i] * br[j];
        }
        __syncthreads();
    }

    #pragma unroll
    for (int i = 0; i < TM; i++)
        #pragma unroll
        for (int j = 0; j < TN; j++)
            C[(long)(rowBase + ty*TM + i) * ldc + (colBase + tx*TN + j)] = alpha * acc[i][j];
}

// ---------------- row softmax (row length 1024, 256 threads) ----------------
__global__ void softmax_kernel(float* __restrict__ X)
{
    const int D = 1024;
    long off = (long)blockIdx.x * D;
    int tid = threadIdx.x;
    float xv[4];
    float m = -INFINITY;
    #pragma unroll
    for (int i = 0; i < 4; i++) { xv[i] = X[off + tid + i*256]; m = fmaxf(m, xv[i]); }

    __shared__ float red[32];
    #pragma unroll
    for (int o = 16; o; o >>= 1) m = fmaxf(m, __shfl_xor_sync(0xffffffffu, m, o));
    if ((tid & 31) == 0) red[tid >> 5] = m;
    __syncthreads();
    if (tid < 32) {
        float v = (tid < 8) ? red[tid] : -INFINITY;
        #pragma unroll
        for (int o = 16; o; o >>= 1) v = fmaxf(v, __shfl_xor_sync(0xffffffffu, v, o));
        if (tid == 0) red[0] = v;
    }
    __syncthreads();
    m = red[0];

    float s = 0.0f;
    #pragma unroll
    for (int i = 0; i < 4; i++) { xv[i] = expf(xv[i] - m); s += xv[i]; }
    __syncthreads();
    #pragma unroll
    for (int o = 16; o; o >>= 1) s += __shfl_xor_sync(0xffffffffu, s, o);
    if ((tid & 31) == 0) red[tid >> 5] = s;
    __syncthreads();
    if (tid < 32) {
        float v = (tid < 8) ? red[tid] : 0.0f;
        #pragma unroll
        for (int o = 16; o; o >>= 1) v += __shfl_xor_sync(0xffffffffu, v, o);
        if (tid == 0) red[0] = v;
    }
    __syncthreads();
    float inv = 1.0f / red[0];
    #pragma unroll
    for (int i = 0; i < 4; i++) X[off + tid + i*256] = xv[i] * inv;
}

// ---------------- out = LN(A + R (+ bias)) * gamma + beta ----------------
__global__ void add_ln_kernel(const float* __restrict__ A, const float* __restrict__ R,
                              const float* __restrict__ bias,
                              const float* __restrict__ gamma, const float* __restrict__ beta,
                              float* __restrict__ out)
{
    const int D = 1024;
    long off = (long)blockIdx.x * D;
    int tid = threadIdx.x;
    float xv[4];
    float s = 0.0f, s2 = 0.0f;
    #pragma unroll
    for (int i = 0; i < 4; i++) {
        int c = tid + i*256;
        float v = A[off + c] + R[off + c];
        if (bias) v += bias[c];
        xv[i] = v; s += v; s2 += v*v;
    }
    __shared__ float rs[32], rs2[32];
    #pragma unroll
    for (int o = 16; o; o >>= 1) { s += __shfl_xor_sync(0xffffffffu, s, o); s2 += __shfl_xor_sync(0xffffffffu, s2, o); }
    if ((tid & 31) == 0) { rs[tid >> 5] = s; rs2[tid >> 5] = s2; }
    __syncthreads();
    if (tid < 32) {
        float a = (tid < 8) ? rs[tid]  : 0.0f;
        float b = (tid < 8) ? rs2[tid] : 0.0f;
        #pragma unroll
        for (int o = 16; o; o >>= 1) { a += __shfl_xor_sync(0xffffffffu, a, o); b += __shfl_xor_sync(0xffffffffu, b, o); }
        if (tid == 0) { rs[0] = a; rs2[0] = b; }
    }
    __syncthreads();
    float mu  = rs[0]  * (1.0f / D);
    float var = rs2[0] * (1.0f / D) - mu * mu;
    float inv = rsqrtf(var + 1e-5f);
    #pragma unroll
    for (int i = 0; i < 4; i++) {
        int c = tid + i*256;
        out[off + c] = (xv[i] - mu) * inv * gamma[c] + beta[c];
    }
}

// ---------------- in-place bias + exact GELU ----------------
__global__ void bias_gelu_kernel(float* __restrict__ X, const float* __restrict__ bias)
{
    long i = (long)blockIdx.x * blockDim.x + threadIdx.x;   // total = 16777216, exact grid
    float x = X[i] + bias[i & (MLPd - 1)];
    X[i] = 0.5f * x * (1.0f + erff(x * 0.70710678118654752f));
}

// ---------------- launch ----------------
typedef void (*noargs)();

extern "C" void kernel_launch(void* const* d_in, const int* in_sizes, int n_in,
                              void* d_out, int out_size)
{
    const float* x      = (const float*)d_in[0];
    const float* enc    = (const float*)d_in[1];
    const float* sa_wq  = (const float*)d_in[2];
    const float* sa_wk  = (const float*)d_in[3];
    const float* sa_wv  = (const float*)d_in[4];
    const float* sa_g   = (const float*)d_in[5];
    const float* sa_b   = (const float*)d_in[6];
    const float* ca_wq  = (const float*)d_in[7];
    const float* ca_wk  = (const float*)d_in[8];
    const float* ca_wv  = (const float*)d_in[9];
    const float* ca_g   = (const float*)d_in[10];
    const float* ca_b   = (const float*)d_in[11];
    const float* w1     = (const float*)d_in[12];
    const float* b1     = (const float*)d_in[13];
    const float* w2     = (const float*)d_in[14];
    const float* b2     = (const float*)d_in[15];
    const float* ff_g   = (const float*)d_in[16];
    const float* ff_b   = (const float*)d_in[17];
    float* out = (float*)d_out;

    float *pq, *pk, *pv, *ps, *psa, *pt, *pdca, *pff;
    cudaGetSymbolAddress((void**)&pq,   g_q);
    cudaGetSymbolAddress((void**)&pk,   g_k);
    cudaGetSymbolAddress((void**)&pv,   g_v);
    cudaGetSymbolAddress((void**)&ps,   g_s);
    cudaGetSymbolAddress((void**)&psa,  g_sa);
    cudaGetSymbolAddress((void**)&pt,   g_t);
    cudaGetSymbolAddress((void**)&pdca, g_dca);
    cudaGetSymbolAddress((void**)&pff,  g_ff);

    const long MM   = (long)Nn * Dd;        // 1048576 per-batch matrix stride
    const long HT   = (long)Nn * DH;        // 65536  per-head T stride
    const long HDCA = (long)Nn * Nn;        // 1048576 per-head attn stride

    #define GEMM128NN gemm_kernel<128,128,16,8,8,false>
    #define GEMM128NT gemm_kernel<128,128,16,8,8,true>
    #define GEMM64NN  gemm_kernel<128, 64,16,8,4,false>

    // ---- Self attention ----
    // q,k,v projections: [4096,1024] @ [1024,1024]
    GEMM128NN<<<dim3(8, 32, 1), 256>>>(x, sa_wq, pq, Dd, Dd, Dd, Dd, 1, 0,0,0,0,0,0, 1.0f);
    GEMM128NN<<<dim3(8, 32, 1), 256>>>(x, sa_wk, pk, Dd, Dd, Dd, Dd, 1, 0,0,0,0,0,0, 1.0f);
    GEMM128NN<<<dim3(8, 32, 1), 256>>>(x, sa_wv, pv, Dd, Dd, Dd, Dd, 1, 0,0,0,0,0,0, 1.0f);
    // dots = (1/32) q k^T   per-batch [1024,1024,1024]
    GEMM128NT<<<dim3(8, 8, Bb), 256>>>(pq, pk, ps, Dd, Dd, Dd, Nn, 1, MM,0, MM,0, MM,0, 0.03125f);
    softmax_kernel<<<Bb*Nn, 256>>>(ps);
    // sa = attn @ v
    GEMM128NN<<<dim3(8, 8, Bb), 256>>>(ps, pv, psa, Nn, Nn, Dd, Dd, 1, MM,0, MM,0, MM,0, 1.0f);
    // sa = LN(sa + x)
    add_ln_kernel<<<BN_TOK, 256>>>(psa, x, nullptr, sa_g, sa_b, psa);

    // ---- Cross attention (kkt folded algebraically) ----
    GEMM128NN<<<dim3(8, 32, 1), 256>>>(psa, ca_wq, pq, Dd, Dd, Dd, Dd, 1, 0,0,0,0,0,0, 1.0f); // qc
    GEMM128NN<<<dim3(8, 32, 1), 256>>>(enc, ca_wk, pk, Dd, Dd, Dd, Dd, 1, 0,0,0,0,0,0, 1.0f); // kc
    GEMM128NN<<<dim3(8, 32, 1), 256>>>(enc, ca_wv, pv, Dd, Dd, Dd, Dd, 1, 0,0,0,0,0,0, 1.0f); // vc
    // T[b,h] = qc_b @ kc[b,:,h*64:..]   [1024,64,1024], 64 batches (b*16+h)
    GEMM64NN<<<dim3(1, 8, Bb*Hh), 256>>>(pq, pk, pt,
                 Dd, Dd, Dd, DH, Hh,
                 MM, 0,  MM, DH,  (long)Hh*HT, HT, 1.0f);
    // dots = (1/64) T @ kc^T            [1024,1024,64]
    GEMM128NT<<<dim3(8, 8, Bb*Hh), 256>>>(pt, pk, pdca,
                 DH, DH, Dd, Nn, Hh,
                 (long)Hh*HT, HT,  MM, DH,  (long)Hh*HDCA, HDCA, 0.015625f);
    softmax_kernel<<<Bb*Hh*Nn, 256>>>(pdca);
    // out[b,:,h*64:..] = attn[b,h] @ vc[b,:,h*64:..]   [1024,64,1024]
    GEMM64NN<<<dim3(1, 8, Bb*Hh), 256>>>(pdca, pv, ps,
                 Dd, Nn, Dd, Dd, Hh,
                 (long)Hh*HDCA, HDCA,  MM, DH,  MM, DH, 1.0f);
    // ca = LN(out + enc)
    add_ln_kernel<<<BN_TOK, 256>>>(ps, enc, nullptr, ca_g, ca_b, psa);

    // ---- FeedForward ----
    // h = ca @ w1   [4096,4096,1024]
    GEMM128NN<<<dim3(32, 32, 1), 256>>>(psa, w1, pff, Dd, Dd, MLPd, MLPd, 1, 0,0,0,0,0,0, 1.0f);
    bias_gelu_kernel<<<(BN_TOK*(long)MLPd)/256, 256>>>(pff, b1);
    // h2 = gelu_h @ w2  [4096,1024,4096]
    GEMM128NN<<<dim3(8, 32, 1), 256>>>(pff, w2, pq, MLPd, MLPd, Dd, Dd, 1, 0,0,0,0,0,0, 1.0f);
    // out = LN(h2 + b2 + ca)
    add_ln_kernel<<<BN_TOK, 256>>>(pq, psa, b2, ff_g, ff_b, out);
}

// round 3
// speedup vs baseline: 4.5717x; 4.5717x over previous
#include <cuda_runtime.h>
#include <math.h>
#include <stdint.h>

// ---------------- problem constants ----------------
#define Bb   4
#define Nn   1024
#define Dd   1024
#define Hh   16
#define DH   64
#define MLPd 4096

#define BN_TOK (Bb*Nn)        // 4096 rows
#define MAT    (Bb*Nn*Dd)     // 4M elems, 16MB

// ---------------- device scratch (no cudaMalloc allowed) ----------------
__device__ float g_q [MAT];                 // q / qc
__device__ float g_k [MAT];                 // k / kc
__device__ float g_v [MAT];                 // v / vc
__device__ float g_s [MAT];                 // sa dots+attn / ca out
__device__ float g_sa[MAT];                 // sa (post-LN) / ca (post-LN)
__device__ float g_t [MAT];                 // T_full / h2
__device__ float g_bt[MAT];                 // kT / kcT
__device__ float g_dca[(long)Bb*Hh*Nn*Nn]; // ca dots/attn (256MB)
__device__ float g_ff[(long)BN_TOK*MLPd];  // FF hidden (64MB)

// ---------------- helpers ----------------
__device__ __forceinline__ uint32_t smem_u32(const void* p) {
    uint32_t a;
    asm("{ .reg .u64 t; cvta.to.shared.u64 t, %1; cvt.u32.u64 %0, t; }" : "=r"(a) : "l"(p));
    return a;
}
#define CP_ASYNC16(dst, src) \
    asm volatile("cp.async.cg.shared.global [%0], [%1], 16;" :: "r"(dst), "l"(src) : "memory")
#define CP_COMMIT() asm volatile("cp.async.commit_group;" ::: "memory")
#define CP_WAIT(n)  asm volatile("cp.async.wait_group %0;" :: "n"(n) : "memory")

__device__ __forceinline__ uint32_t to_tf32(float f) {
    uint32_t u;
    asm("cvt.rna.tf32.f32 %0, %1;" : "=r"(u) : "f"(f));
    return u;
}
__device__ __forceinline__ void mma_tf32(float* d, const uint32_t* a, const uint32_t* b) {
    asm volatile(
        "mma.sync.aligned.m16n8k8.row.col.f32.tf32.tf32.f32 "
        "{%0,%1,%2,%3}, {%4,%5,%6,%7}, {%8,%9}, {%0,%1,%2,%3};"
        : "+f"(d[0]), "+f"(d[1]), "+f"(d[2]), "+f"(d[3])
        : "r"(a[0]), "r"(a[1]), "r"(a[2]), "r"(a[3]), "r"(b[0]), "r"(b[1]));
}

// ================= tf32 mma.sync GEMM =================
// C = alpha * A @ B    A:[M,K] row-major lda, B:[K,N] row-major ldb  (NN)
// BM=128 x BN, BK=32, 256 threads (8 warps as 2x4), 2-stage cp.async pipeline.
// batch via blockIdx.z = zb*bdiv + zh with element strides.
template<int BN>
__global__ void __launch_bounds__(256)
gemm_mma(const float* __restrict__ A, const float* __restrict__ B, float* __restrict__ C,
         int K, int lda, int ldb, int ldc, int bdiv,
         long sAb, long sAh, long sBb, long sBh, long sCb, long sCh, float alpha)
{
    constexpr int BM  = 128, BK = 32;
    constexpr int SA  = BK + 4;          // 36 floats (frag banks: (4g+tig) mod 32 distinct)
    constexpr int SB  = BN + 8;          // 136/72    (frag banks: (8tig+g) mod 32 distinct)
    constexpr int ASZ = BM * SA;
    constexpr int BSZ = BK * SB;
    constexpr int NT  = BN / 32;         // mma n-tiles per warp (4 or 2)
    constexpr int BCH = BK * (BN / 4);   // B-tile 16B chunks (256 or 128)

    extern __shared__ float sm[];
    float* As = sm;
    float* Bs = sm + 2 * ASZ;
    const uint32_t sAs = smem_u32(As), sBs = smem_u32(Bs);

    const int z = blockIdx.z, zb = z / bdiv, zh = z % bdiv;
    A += zb * sAb + zh * sAh;
    B += zb * sBb + zh * sBh;
    C += zb * sCb + zh * sCh;

    const int tid  = threadIdx.x;
    const int wid  = tid >> 5, lane = tid & 31;
    const int g    = lane >> 2, tig = lane & 3;
    const int m0   = (wid >> 2) * 64;           // warp M offset (2 rows of warps)
    const int n0   = (wid & 3) * (BN / 4);      // warp N offset (4 cols of warps)
    const int rowBase = blockIdx.y * BM;
    const int colBase = blockIdx.x * BN;

    float acc[4][NT][4];
    #pragma unroll
    for (int mt = 0; mt < 4; mt++)
        #pragma unroll
        for (int nt = 0; nt < NT; nt++)
            #pragma unroll
            for (int i = 0; i < 4; i++) acc[mt][nt][i] = 0.0f;

    const int nC = K >> 5;

    auto stage_copy = [&](int s, int k0) {
        // A tile: 128 rows x 8 chunks = 1024 chunks, 4 per thread
        #pragma unroll
        for (int j = 0; j < 4; j++) {
            const int cid = tid + j * 256;
            const int r = cid >> 3, c16 = cid & 7;
            const uint32_t dst = sAs + (uint32_t)((s * ASZ + r * SA + c16 * 4) * 4);
            CP_ASYNC16(dst, A + (long)(rowBase + r) * lda + k0 + c16 * 4);
        }
        // B tile: 32 rows x BN/4 chunks
        #pragma unroll
        for (int j = 0; j < (BCH + 255) / 256; j++) {
            const int cid = tid + j * 256;
            if ((BCH & 255) == 0 || cid < BCH) {
                const int r = cid / (BN / 4), c16 = cid % (BN / 4);
                const uint32_t dst = sBs + (uint32_t)((s * BSZ + r * SB + c16 * 4) * 4);
                CP_ASYNC16(dst, B + (long)(k0 + r) * ldb + colBase + c16 * 4);
            }
        }
    };

    auto compute = [&](int s) {
        const float* ab = As + s * ASZ;
        const float* bb = Bs + s * BSZ;
        #pragma unroll
        for (int kk = 0; kk < 4; kk++) {
            const int kb = kk * 8;
            uint32_t af[4][4], bf[NT][2];
            #pragma unroll
            for (int mt = 0; mt < 4; mt++) {
                const int r0 = m0 + mt * 16 + g;
                af[mt][0] = to_tf32(ab[r0 * SA + kb + tig]);
                af[mt][1] = to_tf32(ab[(r0 + 8) * SA + kb + tig]);
                af[mt][2] = to_tf32(ab[r0 * SA + kb + tig + 4]);
                af[mt][3] = to_tf32(ab[(r0 + 8) * SA + kb + tig + 4]);
            }
            #pragma unroll
            for (int nt = 0; nt < NT; nt++) {
                const int cc = n0 + nt * 8 + g;
                bf[nt][0] = to_tf32(bb[(kb + tig) * SB + cc]);
                bf[nt][1] = to_tf32(bb[(kb + tig + 4) * SB + cc]);
            }
            #pragma unroll
            for (int mt = 0; mt < 4; mt++)
                #pragma unroll
                for (int nt = 0; nt < NT; nt++)
                    mma_tf32(acc[mt][nt], af[mt], bf[nt]);
        }
    };

    stage_copy(0, 0);
    CP_COMMIT();
    for (int c = 0; c < nC; c++) {
        const int s = c & 1;
        if (c + 1 < nC) {
            stage_copy((c + 1) & 1, (c + 1) * BK);
            CP_COMMIT();
            CP_WAIT(1);
        } else {
            CP_WAIT(0);
        }
        __syncthreads();
        compute(s);
        __syncthreads();
    }

    // epilogue
    #pragma unroll
    for (int mt = 0; mt < 4; mt++) {
        const int r0 = rowBase + m0 + mt * 16 + g;
        #pragma unroll
        for (int nt = 0; nt < NT; nt++) {
            const int cc = colBase + n0 + nt * 8 + 2 * tig;
            float2 v0, v1;
            v0.x = alpha * acc[mt][nt][0]; v0.y = alpha * acc[mt][nt][1];
            v1.x = alpha * acc[mt][nt][2]; v1.y = alpha * acc[mt][nt][3];
            *reinterpret_cast<float2*>(C + (long)r0 * ldc + cc)       = v0;
            *reinterpret_cast<float2*>(C + (long)(r0 + 8) * ldc + cc) = v1;
        }
    }
}

// ================= transpose: B[C,R] = A[R,C], batched =================
__global__ void transpose_kernel(const float* __restrict__ A, float* __restrict__ B,
                                 int R, int C, long sAb, long sBb)
{
    __shared__ float t[32][33];
    A += (long)blockIdx.z * sAb;
    B += (long)blockIdx.z * sBb;
    const int r0 = blockIdx.y * 32, c0 = blockIdx.x * 32;
    #pragma unroll
    for (int i = threadIdx.y; i < 32; i += 8)
        t[i][threadIdx.x] = A[(long)(r0 + i) * C + c0 + threadIdx.x];
    __syncthreads();
    #pragma unroll
    for (int i = threadIdx.y; i < 32; i += 8)
        B[(long)(c0 + i) * R + r0 + threadIdx.x] = t[threadIdx.x][i];
}

// ================= row softmax (row length 1024, 256 threads) =================
__global__ void softmax_kernel(float* __restrict__ X)
{
    long off = (long)blockIdx.x * 1024;
    int tid = threadIdx.x;
    float xv[4];
    float m = -INFINITY;
    #pragma unroll
    for (int i = 0; i < 4; i++) { xv[i] = X[off + tid + i*256]; m = fmaxf(m, xv[i]); }

    __shared__ float red[32];
    #pragma unroll
    for (int o = 16; o; o >>= 1) m = fmaxf(m, __shfl_xor_sync(0xffffffffu, m, o));
    if ((tid & 31) == 0) red[tid >> 5] = m;
    __syncthreads();
    if (tid < 32) {
        float v = (tid < 8) ? red[tid] : -INFINITY;
        #pragma unroll
        for (int o = 16; o; o >>= 1) v = fmaxf(v, __shfl_xor_sync(0xffffffffu, v, o));
        if (tid == 0) red[0] = v;
    }
    __syncthreads();
    m = red[0];

    float s = 0.0f;
    #pragma unroll
    for (int i = 0; i < 4; i++) { xv[i] = expf(xv[i] - m); s += xv[i]; }
    __syncthreads();
    #pragma unroll
    for (int o = 16; o; o >>= 1) s += __shfl_xor_sync(0xffffffffu, s, o);
    if ((tid & 31) == 0) red[tid >> 5] = s;
    __syncthreads();
    if (tid < 32) {
        float v = (tid < 8) ? red[tid] : 0.0f;
        #pragma unroll
        for (int o = 16; o; o >>= 1) v += __shfl_xor_sync(0xffffffffu, v, o);
        if (tid == 0) red[0] = v;
    }
    __syncthreads();
    float inv = 1.0f / red[0];
    #pragma unroll
    for (int i = 0; i < 4; i++) X[off + tid + i*256] = xv[i] * inv;
}

// ================= out = LN(A + R (+ bias)) * gamma + beta =================
__global__ void add_ln_kernel(const float* __restrict__ A, const float* __restrict__ R,
                              const float* __restrict__ bias,
                              const float* __restrict__ gamma, const float* __restrict__ beta,
                              float* __restrict__ out)
{
    long off = (long)blockIdx.x * 1024;
    int tid = threadIdx.x;
    float xv[4];
    float s = 0.0f, s2 = 0.0f;
    #pragma unroll
    for (int i = 0; i < 4; i++) {
        int c = tid + i*256;
        float v = A[off + c] + R[off + c];
        if (bias) v += bias[c];
        xv[i] = v; s += v; s2 += v*v;
    }
    __shared__ float rs[32], rs2[32];
    #pragma unroll
    for (int o = 16; o; o >>= 1) { s += __shfl_xor_sync(0xffffffffu, s, o); s2 += __shfl_xor_sync(0xffffffffu, s2, o); }
    if ((tid & 31) == 0) { rs[tid >> 5] = s; rs2[tid >> 5] = s2; }
    __syncthreads();
    if (tid < 32) {
        float a = (tid < 8) ? rs[tid]  : 0.0f;
        float b = (tid < 8) ? rs2[tid] : 0.0f;
        #pragma unroll
        for (int o = 16; o; o >>= 1) { a += __shfl_xor_sync(0xffffffffu, a, o); b += __shfl_xor_sync(0xffffffffu, b, o); }
        if (tid == 0) { rs[0] = a; rs2[0] = b; }
    }
    __syncthreads();
    float mu  = rs[0]  * (1.0f / 1024.0f);
    float var = rs2[0] * (1.0f / 1024.0f) - mu * mu;
    float inv = rsqrtf(var + 1e-5f);
    #pragma unroll
    for (int i = 0; i < 4; i++) {
        int c = tid + i*256;
        out[off + c] = (xv[i] - mu) * inv * gamma[c] + beta[c];
    }
}

// ================= in-place bias + exact GELU =================
__global__ void bias_gelu_kernel(float* __restrict__ X, const float* __restrict__ bias)
{
    long i = (long)blockIdx.x * blockDim.x + threadIdx.x;
    float x = X[i] + bias[i & (MLPd - 1)];
    X[i] = 0.5f * x * (1.0f + erff(x * 0.70710678118654752f));
}

// ================= launch =================
extern "C" void kernel_launch(void* const* d_in, const int* in_sizes, int n_in,
                              void* d_out, int out_size)
{
    const float* x      = (const float*)d_in[0];
    const float* enc    = (const float*)d_in[1];
    const float* sa_wq  = (const float*)d_in[2];
    const float* sa_wk  = (const float*)d_in[3];
    const float* sa_wv  = (const float*)d_in[4];
    const float* sa_g   = (const float*)d_in[5];
    const float* sa_b   = (const float*)d_in[6];
    const float* ca_wq  = (const float*)d_in[7];
    const float* ca_wk  = (const float*)d_in[8];
    const float* ca_wv  = (const float*)d_in[9];
    const float* ca_g   = (const float*)d_in[10];
    const float* ca_b   = (const float*)d_in[11];
    const float* w1     = (const float*)d_in[12];
    const float* b1     = (const float*)d_in[13];
    const float* w2     = (const float*)d_in[14];
    const float* b2     = (const float*)d_in[15];
    const float* ff_g   = (const float*)d_in[16];
    const float* ff_b   = (const float*)d_in[17];
    float* out = (float*)d_out;

    float *pq, *pk, *pv, *ps, *psa, *pt, *pbt, *pdca, *pff;
    cudaGetSymbolAddress((void**)&pq,   g_q);
    cudaGetSymbolAddress((void**)&pk,   g_k);
    cudaGetSymbolAddress((void**)&pv,   g_v);
    cudaGetSymbolAddress((void**)&ps,   g_s);
    cudaGetSymbolAddress((void**)&psa,  g_sa);
    cudaGetSymbolAddress((void**)&pt,   g_t);
    cudaGetSymbolAddress((void**)&pbt,  g_bt);
    cudaGetSymbolAddress((void**)&pdca, g_dca);
    cudaGetSymbolAddress((void**)&pff,  g_ff);

    const long MM   = (long)Nn * Dd;     // per-batch matrix stride
    const long HDCA = (long)Nn * Nn;     // per-head attn stride

    // dynamic smem sizes
    constexpr int S128 = (2 * 128 * 36 + 2 * 32 * 136) * 4; // 71680 B
    constexpr int S64  = (2 * 128 * 36 + 2 * 32 * 72) * 4;  // 55296 B
    cudaFuncSetAttribute((const void*)gemm_mma<128>, cudaFuncAttributeMaxDynamicSharedMemorySize, S128);
    cudaFuncSetAttribute((const void*)gemm_mma<64>,  cudaFuncAttributeMaxDynamicSharedMemorySize, S64);

    const dim3 T32(32, 8, 1);

    // ---- Self attention ----
    gemm_mma<128><<<dim3(8,32,1), 256, S128>>>(x, sa_wq, pq, Dd, Dd, Dd, Dd, 1, 0,0,0,0,0,0, 1.0f);
    gemm_mma<128><<<dim3(8,32,1), 256, S128>>>(x, sa_wk, pk, Dd, Dd, Dd, Dd, 1, 0,0,0,0,0,0, 1.0f);
    gemm_mma<128><<<dim3(8,32,1), 256, S128>>>(x, sa_wv, pv, Dd, Dd, Dd, Dd, 1, 0,0,0,0,0,0, 1.0f);
    // kT per batch
    transpose_kernel<<<dim3(32,32,Bb), T32>>>(pk, pbt, Nn, Dd, MM, MM);
    // dots = (1/32) q @ kT
    gemm_mma<128><<<dim3(8,8,Bb), 256, S128>>>(pq, pbt, ps, Dd, Dd, Nn, Nn, 1, MM,0, MM,0, MM,0, 0.03125f);
    softmax_kernel<<<Bb*Nn, 256>>>(ps);
    // sa = attn @ v (NN)
    gemm_mma<128><<<dim3(8,8,Bb), 256, S128>>>(ps, pv, psa, Nn, Nn, Dd, Dd, 1, MM,0, MM,0, MM,0, 1.0f);
    add_ln_kernel<<<BN_TOK, 256>>>(psa, x, nullptr, sa_g, sa_b, psa);

    // ---- Cross attention (kkt folded: dots_h = (qc@kc_h) @ kc_h^T / 64) ----
    gemm_mma<128><<<dim3(8,32,1), 256, S128>>>(psa, ca_wq, pq, Dd, Dd, Dd, Dd, 1, 0,0,0,0,0,0, 1.0f); // qc
    gemm_mma<128><<<dim3(8,32,1), 256, S128>>>(enc, ca_wk, pk, Dd, Dd, Dd, Dd, 1, 0,0,0,0,0,0, 1.0f); // kc
    gemm_mma<128><<<dim3(8,32,1), 256, S128>>>(enc, ca_wv, pv, Dd, Dd, Dd, Dd, 1, 0,0,0,0,0,0, 1.0f); // vc
    // T_full = qc @ kc  (NN, per batch; head slices are just column blocks)
    gemm_mma<128><<<dim3(8,8,Bb), 256, S128>>>(pq, pk, pt, Dd, Dd, Dd, Dd, 1, MM,0, MM,0, MM,0, 1.0f);
    // kcT per batch
    transpose_kernel<<<dim3(32,32,Bb), T32>>>(pk, pbt, Nn, Dd, MM, MM);
    // dca[b,h] = (1/64) T_full[:, h*64:] @ kcT[h*64:, :]   (NN, K=64)
    gemm_mma<128><<<dim3(8,8,Bb*Hh), 256, S128>>>(pt, pbt, pdca,
                 DH, Dd, Nn, Nn, Hh,
                 MM, (long)DH,  MM, (long)DH*Nn,  (long)Hh*HDCA, HDCA, 0.015625f);
    softmax_kernel<<<Bb*Hh*Nn, 256>>>(pdca);
    // out[:, h*64:] = attn[b,h] @ vc[:, h*64:]  (NN, N=64)
    gemm_mma<64><<<dim3(1,8,Bb*Hh), 256, S64>>>(pdca, pv, ps,
                 Nn, Nn, Dd, Dd, Hh,
                 (long)Hh*HDCA, HDCA,  MM, (long)DH,  MM, (long)DH, 1.0f);
    add_ln_kernel<<<BN_TOK, 256>>>(ps, enc, nullptr, ca_g, ca_b, psa);

    // ---- FeedForward ----
    gemm_mma<128><<<dim3(32,32,1), 256, S128>>>(psa, w1, pff, Dd, Dd, MLPd, MLPd, 1, 0,0,0,0,0,0, 1.0f);
    bias_gelu_kernel<<<(BN_TOK*(long)MLPd)/256, 256>>>(pff, b1);
    gemm_mma<128><<<dim3(8,32,1), 256, S128>>>(pff, w2, pt, MLPd, MLPd, Dd, Dd, 1, 0,0,0,0,0,0, 1.0f);
    add_ln_kernel<<<BN_TOK, 256>>>(pt, psa, b2, ff_g, ff_b, out);
}

// round 5
// speedup vs baseline: 4.8545x; 1.0619x over previous
#include <cuda_runtime.h>
#include <math.h>
#include <stdint.h>

// ---------------- problem constants ----------------
#define Bb   4
#define Nn   1024
#define Dd   1024
#define Hh   16
#define DH   64
#define MLPd 4096

#define BN_TOK (Bb*Nn)        // 4096 rows
#define MAT    (Bb*Nn*Dd)     // 4M elems, 16MB

// ---------------- device scratch ----------------
__device__ float g_q [MAT];                 // q / qc
__device__ float g_k [MAT];                 // k / kc
__device__ float g_v [MAT];                 // v / vc
__device__ float g_s [MAT];                 // sa dots+attn / ca flash out
__device__ float g_sa[MAT];                 // sa (post-LN) / ca (post-LN)
__device__ float g_t [MAT];                 // T_full / h2
__device__ float g_ff[(long)BN_TOK*MLPd];   // FF hidden (64MB)

// ---------------- helpers ----------------
__device__ __forceinline__ uint32_t smem_u32(const void* p) {
    uint32_t a;
    asm("{ .reg .u64 t; cvta.to.shared.u64 t, %1; cvt.u32.u64 %0, t; }" : "=r"(a) : "l"(p));
    return a;
}
#define CP_ASYNC16(dst, src) \
    asm volatile("cp.async.cg.shared.global [%0], [%1], 16;" :: "r"(dst), "l"(src) : "memory")
#define CP_COMMIT() asm volatile("cp.async.commit_group;" ::: "memory")
#define CP_WAIT(n)  asm volatile("cp.async.wait_group %0;" :: "n"(n) : "memory")

__device__ __forceinline__ uint32_t to_tf32(float f) {
    uint32_t u;
    asm("cvt.rna.tf32.f32 %0, %1;" : "=r"(u) : "f"(f));
    return u;
}
__device__ __forceinline__ void mma_tf32(float* d, const uint32_t* a, const uint32_t* b) {
    asm volatile(
        "mma.sync.aligned.m16n8k8.row.col.f32.tf32.tf32.f32 "
        "{%0,%1,%2,%3}, {%4,%5,%6,%7}, {%8,%9}, {%0,%1,%2,%3};"
        : "+f"(d[0]), "+f"(d[1]), "+f"(d[2]), "+f"(d[3])
        : "r"(a[0]), "r"(a[1]), "r"(a[2]), "r"(a[3]), "r"(b[0]), "r"(b[1]));
}
__device__ __forceinline__ float gelu_exact(float x) {
    return 0.5f * x * (1.0f + erff(x * 0.70710678118654752f));
}

// ================= tf32 mma.sync GEMM (3-stage pipeline) =================
// TRB=false: C = alpha*A@B,   A:[M,K] lda, B:[K,N] ldb (row-major)
// TRB=true : C = alpha*A@B^T, A:[M,K] lda, B:[N,K] ldb (row-major)
// GELU=true: C = gelu(A@B + bias[col])
// BM=128, BN=128, BK=32, 256 threads (2x4 warps, 64x32 warp tiles).
template<bool TRB, bool GELU>
__global__ void __launch_bounds__(256)
gemm_mma(const float* __restrict__ A, const float* __restrict__ B, float* __restrict__ C,
         const float* __restrict__ bias,
         int K, int lda, int ldb, int ldc, int bdiv,
         long sAb, long sAh, long sBb, long sBh, long sCb, long sCh, float alpha)
{
    constexpr int BM  = 128, BN = 128, BK = 32;
    constexpr int SA  = BK + 4;                    // A smem row stride (36)
    constexpr int SBN = TRB ? (BK + 4) : (BN + 8); // B smem row stride
    constexpr int ASZ = BM * SA;                   // 4608 floats
    constexpr int BSZ = TRB ? (BN * SBN) : (BK * SBN); // 4608 / 4352

    extern __shared__ float sm[];
    float* As = sm;
    float* Bs = sm + 3 * ASZ;
    const uint32_t sAs = smem_u32(As), sBs = smem_u32(Bs);

    const int z = blockIdx.z, zb = z / bdiv, zh = z % bdiv;
    A += zb * sAb + zh * sAh;
    B += zb * sBb + zh * sBh;
    C += zb * sCb + zh * sCh;

    const int tid  = threadIdx.x;
    const int wid  = tid >> 5, lane = tid & 31;
    const int g    = lane >> 2, tig = lane & 3;
    const int m0   = (wid >> 2) * 64;
    const int n0   = (wid & 3) * 32;
    const int rowBase = blockIdx.y * BM;
    const int colBase = blockIdx.x * BN;

    float acc[4][4][4];
    #pragma unroll
    for (int mt = 0; mt < 4; mt++)
        #pragma unroll
        for (int nt = 0; nt < 4; nt++)
            #pragma unroll
            for (int i = 0; i < 4; i++) acc[mt][nt][i] = 0.0f;

    const int nC = K >> 5;

    auto stage_copy = [&](int s, int k0) {
        // A tile: 128 rows x 8 f4-chunks
        #pragma unroll
        for (int j = 0; j < 4; j++) {
            const int cid = tid + j * 256;
            const int r = cid >> 3, c16 = cid & 7;
            CP_ASYNC16(sAs + (uint32_t)((s * ASZ + r * SA + c16 * 4) * 4),
                       A + (long)(rowBase + r) * lda + k0 + c16 * 4);
        }
        if (TRB) {
            // B tile: 128 N-rows x 8 f4-chunks of K
            #pragma unroll
            for (int j = 0; j < 4; j++) {
                const int cid = tid + j * 256;
                const int r = cid >> 3, c16 = cid & 7;
                CP_ASYNC16(sBs + (uint32_t)((s * BSZ + r * SBN + c16 * 4) * 4),
                           B + (long)(colBase + r) * ldb + k0 + c16 * 4);
            }
        } else {
            // B tile: 32 K-rows x 32 f4-chunks of N
            #pragma unroll
            for (int j = 0; j < 4; j++) {
                const int cid = tid + j * 256;
                const int r = cid >> 5, c16 = cid & 31;
                CP_ASYNC16(sBs + (uint32_t)((s * BSZ + r * SBN + c16 * 4) * 4),
                           B + (long)(k0 + r) * ldb + colBase + c16 * 4);
            }
        }
    };

    auto compute = [&](int s) {
        const float* ab = As + s * ASZ;
        const float* bb = Bs + s * BSZ;
        #pragma unroll
        for (int kk = 0; kk < 4; kk++) {
            const int kb = kk * 8;
            uint32_t af[4][4], bf[4][2];
            #pragma unroll
            for (int mt = 0; mt < 4; mt++) {
                const int r0 = m0 + mt * 16 + g;
                af[mt][0] = to_tf32(ab[r0 * SA + kb + tig]);
                af[mt][1] = to_tf32(ab[(r0 + 8) * SA + kb + tig]);
                af[mt][2] = to_tf32(ab[r0 * SA + kb + tig + 4]);
                af[mt][3] = to_tf32(ab[(r0 + 8) * SA + kb + tig + 4]);
            }
            #pragma unroll
            for (int nt = 0; nt < 4; nt++) {
                const int cc = n0 + nt * 8 + g;
                if (TRB) {
                    bf[nt][0] = to_tf32(bb[cc * SBN + kb + tig]);
                    bf[nt][1] = to_tf32(bb[cc * SBN + kb + tig + 4]);
                } else {
                    bf[nt][0] = to_tf32(bb[(kb + tig) * SBN + cc]);
                    bf[nt][1] = to_tf32(bb[(kb + tig + 4) * SBN + cc]);
                }
            }
            #pragma unroll
            for (int mt = 0; mt < 4; mt++)
                #pragma unroll
                for (int nt = 0; nt < 4; nt++)
                    mma_tf32(acc[mt][nt], af[mt], bf[nt]);
        }
    };

    // 3-stage pipeline, one barrier per chunk
    stage_copy(0, 0); CP_COMMIT();
    stage_copy(1, BK); CP_COMMIT();
    for (int c = 0; c < nC; c++) {
        if (c + 1 < nC) { CP_WAIT(1); } else { CP_WAIT(0); }
        __syncthreads();
        compute(c % 3);
        if (c + 2 < nC) { stage_copy((c + 2) % 3, (c + 2) * BK); CP_COMMIT(); }
    }

    // epilogue
    #pragma unroll
    for (int mt = 0; mt < 4; mt++) {
        const int r0 = rowBase + m0 + mt * 16 + g;
        #pragma unroll
        for (int nt = 0; nt < 4; nt++) {
            const int cc = colBase + n0 + nt * 8 + 2 * tig;
            float v0 = acc[mt][nt][0], v1 = acc[mt][nt][1];
            float v2 = acc[mt][nt][2], v3 = acc[mt][nt][3];
            if (GELU) {
                const float b0 = bias[cc], b1 = bias[cc + 1];
                v0 = gelu_exact(v0 + b0); v1 = gelu_exact(v1 + b1);
                v2 = gelu_exact(v2 + b0); v3 = gelu_exact(v3 + b1);
            } else {
                v0 *= alpha; v1 *= alpha; v2 *= alpha; v3 *= alpha;
            }
            *reinterpret_cast<float2*>(C + (long)r0 * ldc + cc)       = make_float2(v0, v1);
            *reinterpret_cast<float2*>(C + (long)(r0 + 8) * ldc + cc) = make_float2(v2, v3);
        }
    }
}

// ================= fused CA flash attention =================
// Per CTA: 128 query rows x one head. S = (T_h @ kc_h^T)/64, P = exp(S),
// O = (P @ vc_h) / rowsum(P).  No max-subtraction (scores are O(1)).
// grid: x = row tile (8), y = head (16), z = batch (4). 256 threads.
#define FQ_OFF 0
#define FK_OFF 8704
#define FP_OFF 17408
#define FV_OFF 34304
#define FLASH_SMEM ((34304 + 64*132) * 4)   // 171008 B

__global__ void __launch_bounds__(256)
flash_ca(const float* __restrict__ T, const float* __restrict__ KC,
         const float* __restrict__ VC, float* __restrict__ O)
{
    extern __shared__ float sm[];
    float* Qs = sm + FQ_OFF;   // [128][68]
    float* Ks = sm + FK_OFF;   // [128][68]
    float* Ps = sm + FP_OFF;   // [128][132]
    float* Vt = sm + FV_OFF;   // [64][132]  (V^T)
    const uint32_t sQ = smem_u32(Qs), sK = smem_u32(Ks);

    const int b = blockIdx.z, h = blockIdx.y;
    const int rowBase = blockIdx.x * 128;
    const float* Tb = T  + ((long)b * Nn + rowBase) * Dd + h * DH;
    const float* Kb = KC + (long)b * Nn * Dd + h * DH;
    const float* Vb = VC + (long)b * Nn * Dd + h * DH;
    float* Ob       = O  + ((long)b * Nn + rowBase) * Dd + h * DH;

    const int tid = threadIdx.x;
    const int wid = tid >> 5, lane = tid & 31;
    const int g = lane >> 2, tig = lane & 3;
    const int m0  = (wid >> 2) * 64;
    const int n0  = (wid & 3) * 32;   // S-phase cols
    const int n0v = (wid & 3) * 16;   // PV-phase cols

    float accO[4][2][4];
    float den[4][2];
    #pragma unroll
    for (int mt = 0; mt < 4; mt++) {
        den[mt][0] = den[mt][1] = 0.0f;
        #pragma unroll
        for (int nt = 0; nt < 2; nt++)
            #pragma unroll
            for (int i = 0; i < 4; i++) accO[mt][nt][i] = 0.0f;
    }

    // prologue: Q tile (once) + K tile 0.
    // 128 rows x 64 floats = 128x16 f4-chunks = 2048 chunks -> 8 iters of 256 thr.
    #pragma unroll
    for (int j = 0; j < 8; j++) {
        const int cid = tid + j * 256;
        const int r = cid >> 4, c16 = cid & 15;
        CP_ASYNC16(sQ + (uint32_t)((r * 68 + c16 * 4) * 4), Tb + (long)r * Dd + c16 * 4);
        CP_ASYNC16(sK + (uint32_t)((r * 68 + c16 * 4) * 4), Kb + (long)r * Dd + c16 * 4);
    }
    CP_COMMIT();

    const int jrow = tid >> 1;            // V^T loader: key row
    const int dhalf = (tid & 1) * 32;     // d half

    for (int jt = 0; jt < 8; jt++) {
        if (jt > 0) {
            #pragma unroll
            for (int j = 0; j < 8; j++) {
                const int cid = tid + j * 256;
                const int r = cid >> 4, c16 = cid & 15;
                CP_ASYNC16(sK + (uint32_t)((r * 68 + c16 * 4) * 4),
                           Kb + (long)(jt * 128 + r) * Dd + c16 * 4);
            }
            CP_COMMIT();
        }
        // V tile into regs (overlaps cp.async)
        float4 vreg[8];
        #pragma unroll
        for (int i = 0; i < 8; i++)
            vreg[i] = *reinterpret_cast<const float4*>(Vb + (long)(jt * 128 + jrow) * Dd + dhalf + i * 4);

        CP_WAIT(0);
        __syncthreads();

        // V^T store
        #pragma unroll
        for (int i = 0; i < 8; i++) {
            const int d = dhalf + i * 4;
            Vt[(d + 0) * 132 + jrow] = vreg[i].x;
            Vt[(d + 1) * 132 + jrow] = vreg[i].y;
            Vt[(d + 2) * 132 + jrow] = vreg[i].z;
            Vt[(d + 3) * 132 + jrow] = vreg[i].w;
        }

        // S = Q @ K^T (K-dim 64)
        float accS[4][4][4];
        #pragma unroll
        for (int mt = 0; mt < 4; mt++)
            #pragma unroll
            for (int nt = 0; nt < 4; nt++)
                #pragma unroll
                for (int i = 0; i < 4; i++) accS[mt][nt][i] = 0.0f;
        #pragma unroll
        for (int kk = 0; kk < 8; kk++) {
            const int kb = kk * 8;
            uint32_t af[4][4], bf[4][2];
            #pragma unroll
            for (int mt = 0; mt < 4; mt++) {
                const int r0 = m0 + mt * 16 + g;
                af[mt][0] = to_tf32(Qs[r0 * 68 + kb + tig]);
                af[mt][1] = to_tf32(Qs[(r0 + 8) * 68 + kb + tig]);
                af[mt][2] = to_tf32(Qs[r0 * 68 + kb + tig + 4]);
                af[mt][3] = to_tf32(Qs[(r0 + 8) * 68 + kb + tig + 4]);
            }
            #pragma unroll
            for (int nt = 0; nt < 4; nt++) {
                const int cc = n0 + nt * 8 + g;
                bf[nt][0] = to_tf32(Ks[cc * 68 + kb + tig]);
                bf[nt][1] = to_tf32(Ks[cc * 68 + kb + tig + 4]);
            }
            #pragma unroll
            for (int mt = 0; mt < 4; mt++)
                #pragma unroll
                for (int nt = 0; nt < 4; nt++)
                    mma_tf32(accS[mt][nt], af[mt], bf[nt]);
        }

        // exp, denominator partials, P store
        #pragma unroll
        for (int mt = 0; mt < 4; mt++) {
            const int r0 = m0 + mt * 16 + g;
            #pragma unroll
            for (int nt = 0; nt < 4; nt++) {
                const int col = n0 + nt * 8 + 2 * tig;
                const float e0 = expf(accS[mt][nt][0] * 0.015625f);
                const float e1 = expf(accS[mt][nt][1] * 0.015625f);
                const float e2 = expf(accS[mt][nt][2] * 0.015625f);
                const float e3 = expf(accS[mt][nt][3] * 0.015625f);
                den[mt][0] += e0 + e1;
                den[mt][1] += e2 + e3;
                *reinterpret_cast<float2*>(&Ps[r0 * 132 + col])       = make_float2(e0, e1);
                *reinterpret_cast<float2*>(&Ps[(r0 + 8) * 132 + col]) = make_float2(e2, e3);
            }
        }
        __syncthreads();   // P + V^T visible

        // O += P @ V   (K-dim 128)
        #pragma unroll
        for (int kk = 0; kk < 16; kk++) {
            const int kb = kk * 8;
            uint32_t af[4][4], bf[2][2];
            #pragma unroll
            for (int mt = 0; mt < 4; mt++) {
                const int r0 = m0 + mt * 16 + g;
                af[mt][0] = to_tf32(Ps[r0 * 132 + kb + tig]);
                af[mt][1] = to_tf32(Ps[(r0 + 8) * 132 + kb + tig]);
                af[mt][2] = to_tf32(Ps[r0 * 132 + kb + tig + 4]);
                af[mt][3] = to_tf32(Ps[(r0 + 8) * 132 + kb + tig + 4]);
            }
            #pragma unroll
            for (int nt = 0; nt < 2; nt++) {
                const int dc = n0v + nt * 8 + g;
                bf[nt][0] = to_tf32(Vt[dc * 132 + kb + tig]);
                bf[nt][1] = to_tf32(Vt[dc * 132 + kb + tig + 4]);
            }
            #pragma unroll
            for (int mt = 0; mt < 4; mt++)
                #pragma unroll
                for (int nt = 0; nt < 2; nt++)
                    mma_tf32(accO[mt][nt], af[mt], bf[nt]);
        }
        __syncthreads();   // protect Ks/Vt/Ps for next tile
    }

    // denominator: reduce over tig lanes, then across 4 column-warps via smem
    float* Dred = Ps;   // reuse [128][4]
    const int nc = wid & 3;
    #pragma unroll
    for (int mt = 0; mt < 4; mt++) {
        float d0 = den[mt][0], d1 = den[mt][1];
        d0 += __shfl_xor_sync(0xffffffffu, d0, 1); d0 += __shfl_xor_sync(0xffffffffu, d0, 2);
        d1 += __shfl_xor_sync(0xffffffffu, d1, 1); d1 += __shfl_xor_sync(0xffffffffu, d1, 2);
        if (tig == 0) {
            Dred[(m0 + mt * 16 + g) * 4 + nc]     = d0;
            Dred[(m0 + mt * 16 + g + 8) * 4 + nc] = d1;
        }
    }
    __syncthreads();

    #pragma unroll
    for (int mt = 0; mt < 4; mt++) {
        const int r0 = m0 + mt * 16 + g;
        const float4 q0 = *reinterpret_cast<const float4*>(&Dred[r0 * 4]);
        const float4 q1 = *reinterpret_cast<const float4*>(&Dred[(r0 + 8) * 4]);
        const float inv0 = 1.0f / (q0.x + q0.y + q0.z + q0.w);
        const float inv1 = 1.0f / (q1.x + q1.y + q1.z + q1.w);
        #pragma unroll
        for (int nt = 0; nt < 2; nt++) {
            const int col = n0v + nt * 8 + 2 * tig;
            *reinterpret_cast<float2*>(Ob + (long)r0 * Dd + col) =
                make_float2(accO[mt][nt][0] * inv0, accO[mt][nt][1] * inv0);
            *reinterpret_cast<float2*>(Ob + (long)(r0 + 8) * Dd + col) =
                make_float2(accO[mt][nt][2] * inv1, accO[mt][nt][3] * inv1);
        }
    }
}

// ================= row softmax (row length 1024, 256 threads) =================
__global__ void softmax_kernel(float* __restrict__ X)
{
    long off = (long)blockIdx.x * 1024;
    int tid = threadIdx.x;
    float xv[4];
    float m = -INFINITY;
    #pragma unroll
    for (int i = 0; i < 4; i++) { xv[i] = X[off + tid + i*256]; m = fmaxf(m, xv[i]); }

    __shared__ float red[32];
    #pragma unroll
    for (int o = 16; o; o >>= 1) m = fmaxf(m, __shfl_xor_sync(0xffffffffu, m, o));
    if ((tid & 31) == 0) red[tid >> 5] = m;
    __syncthreads();
    if (tid < 32) {
        float v = (tid < 8) ? red[tid] : -INFINITY;
        #pragma unroll
        for (int o = 16; o; o >>= 1) v = fmaxf(v, __shfl_xor_sync(0xffffffffu, v, o));
        if (tid == 0) red[0] = v;
    }
    __syncthreads();
    m = red[0];

    float s = 0.0f;
    #pragma unroll
    for (int i = 0; i < 4; i++) { xv[i] = expf(xv[i] - m); s += xv[i]; }
    __syncthreads();
    #pragma unroll
    for (int o = 16; o; o >>= 1) s += __shfl_xor_sync(0xffffffffu, s, o);
    if ((tid & 31) == 0) red[tid >> 5] = s;
    __syncthreads();
    if (tid < 32) {
        float v = (tid < 8) ? red[tid] : 0.0f;
        #pragma unroll
        for (int o = 16; o; o >>= 1) v += __shfl_xor_sync(0xffffffffu, v, o);
        if (tid == 0) red[0] = v;
    }
    __syncthreads();
    float inv = 1.0f / red[0];
    #pragma unroll
    for (int i = 0; i < 4; i++) X[off + tid + i*256] = xv[i] * inv;
}

// ================= out = LN(A + R (+ bias)) * gamma + beta =================
__global__ void add_ln_kernel(const float* __restrict__ A, const float* __restrict__ R,
                              const float* __restrict__ bias,
                              const float* __restrict__ gamma, const float* __restrict__ beta,
                              float* __restrict__ out)
{
    long off = (long)blockIdx.x * 1024;
    int tid = threadIdx.x;
    float xv[4];
    float s = 0.0f, s2 = 0.0f;
    #pragma unroll
    for (int i = 0; i < 4; i++) {
        int c = tid + i*256;
        float v = A[off + c] + R[off + c];
        if (bias) v += bias[c];
        xv[i] = v; s += v; s2 += v*v;
    }
    __shared__ float rs[32], rs2[32];
    #pragma unroll
    for (int o = 16; o; o >>= 1) { s += __shfl_xor_sync(0xffffffffu, s, o); s2 += __shfl_xor_sync(0xffffffffu, s2, o); }
    if ((tid & 31) == 0) { rs[tid >> 5] = s; rs2[tid >> 5] = s2; }
    __syncthreads();
    if (tid < 32) {
        float a = (tid < 8) ? rs[tid]  : 0.0f;
        float b = (tid < 8) ? rs2[tid] : 0.0f;
        #pragma unroll
        for (int o = 16; o; o >>= 1) { a += __shfl_xor_sync(0xffffffffu, a, o); b += __shfl_xor_sync(0xffffffffu, b, o); }
        if (tid == 0) { rs[0] = a; rs2[0] = b; }
    }
    __syncthreads();
    float mu  = rs[0]  * (1.0f / 1024.0f);
    float var = rs2[0] * (1.0f / 1024.0f) - mu * mu;
    float inv = rsqrtf(var + 1e-5f);
    #pragma unroll
    for (int i = 0; i < 4; i++) {
        int c = tid + i*256;
        out[off + c] = (xv[i] - mu) * inv * gamma[c] + beta[c];
    }
}

// ================= launch =================
extern "C" void kernel_launch(void* const* d_in, const int* in_sizes, int n_in,
                              void* d_out, int out_size)
{
    const float* x      = (const float*)d_in[0];
    const float* enc    = (const float*)d_in[1];
    const float* sa_wq  = (const float*)d_in[2];
    const float* sa_wk  = (const float*)d_in[3];
    const float* sa_wv  = (const float*)d_in[4];
    const float* sa_g   = (const float*)d_in[5];
    const float* sa_b   = (const float*)d_in[6];
    const float* ca_wq  = (const float*)d_in[7];
    const float* ca_wk  = (const float*)d_in[8];
    const float* ca_wv  = (const float*)d_in[9];
    const float* ca_g   = (const float*)d_in[10];
    const float* ca_b   = (const float*)d_in[11];
    const float* w1     = (const float*)d_in[12];
    const float* b1     = (const float*)d_in[13];
    const float* w2     = (const float*)d_in[14];
    const float* b2     = (const float*)d_in[15];
    const float* ff_g   = (const float*)d_in[16];
    const float* ff_b   = (const float*)d_in[17];
    float* out = (float*)d_out;

    float *pq, *pk, *pv, *ps, *psa, *pt, *pff;
    cudaGetSymbolAddress((void**)&pq,  g_q);
    cudaGetSymbolAddress((void**)&pk,  g_k);
    cudaGetSymbolAddress((void**)&pv,  g_v);
    cudaGetSymbolAddress((void**)&ps,  g_s);
    cudaGetSymbolAddress((void**)&psa, g_sa);
    cudaGetSymbolAddress((void**)&pt,  g_t);
    cudaGetSymbolAddress((void**)&pff, g_ff);

    const long MM = (long)Nn * Dd;

    // smem: 3-stage
    constexpr int S_NN = (3 * 128 * 36 + 3 * 32 * 136) * 4;  // 107520 B
    constexpr int S_NT = (3 * 128 * 36 + 3 * 128 * 36) * 4;  // 110592 B
    cudaFuncSetAttribute((const void*)gemm_mma<false,false>, cudaFuncAttributeMaxDynamicSharedMemorySize, S_NN);
    cudaFuncSetAttribute((const void*)gemm_mma<false,true>,  cudaFuncAttributeMaxDynamicSharedMemorySize, S_NN);
    cudaFuncSetAttribute((const void*)gemm_mma<true,false>,  cudaFuncAttributeMaxDynamicSharedMemorySize, S_NT);
    cudaFuncSetAttribute((const void*)flash_ca, cudaFuncAttributeMaxDynamicSharedMemorySize, FLASH_SMEM);

    #define GEMM_NN gemm_mma<false,false>
    #define GEMM_NT gemm_mma<true,false>
    #define GEMM_GE gemm_mma<false,true>

    // ---- Self attention ----
    GEMM_NN<<<dim3(8,32,1), 256, S_NN>>>(x, sa_wq, pq, nullptr, Dd, Dd, Dd, Dd, 1, 0,0,0,0,0,0, 1.0f);
    GEMM_NN<<<dim3(8,32,1), 256, S_NN>>>(x, sa_wk, pk, nullptr, Dd, Dd, Dd, Dd, 1, 0,0,0,0,0,0, 1.0f);
    GEMM_NN<<<dim3(8,32,1), 256, S_NN>>>(x, sa_wv, pv, nullptr, Dd, Dd, Dd, Dd, 1, 0,0,0,0,0,0, 1.0f);
    // dots = (1/32) q @ k^T   (NT: B = k [N,K] row-major)
    GEMM_NT<<<dim3(8,8,Bb), 256, S_NT>>>(pq, pk, ps, nullptr, Dd, Dd, Dd, Nn, 1, MM,0, MM,0, MM,0, 0.03125f);
    softmax_kernel<<<Bb*Nn, 256>>>(ps);
    GEMM_NN<<<dim3(8,8,Bb), 256, S_NN>>>(ps, pv, psa, nullptr, Nn, Nn, Dd, Dd, 1, MM,0, MM,0, MM,0, 1.0f);
    add_ln_kernel<<<BN_TOK, 256>>>(psa, x, nullptr, sa_g, sa_b, psa);

    // ---- Cross attention (kkt folded; softmax/PV fused flash) ----
    GEMM_NN<<<dim3(8,32,1), 256, S_NN>>>(psa, ca_wq, pq, nullptr, Dd, Dd, Dd, Dd, 1, 0,0,0,0,0,0, 1.0f); // qc
    GEMM_NN<<<dim3(8,32,1), 256, S_NN>>>(enc, ca_wk, pk, nullptr, Dd, Dd, Dd, Dd, 1, 0,0,0,0,0,0, 1.0f); // kc
    GEMM_NN<<<dim3(8,32,1), 256, S_NN>>>(enc, ca_wv, pv, nullptr, Dd, Dd, Dd, Dd, 1, 0,0,0,0,0,0, 1.0f); // vc
    // T_full = qc @ kc (NN, per batch)
    GEMM_NN<<<dim3(8,8,Bb), 256, S_NN>>>(pq, pk, pt, nullptr, Dd, Dd, Dd, Dd, 1, MM,0, MM,0, MM,0, 1.0f);
    // fused: S = T_h @ kc_h^T / 64, softmax, @ vc_h
    flash_ca<<<dim3(8,16,4), 256, FLASH_SMEM>>>(pt, pk, pv, ps);
    add_ln_kernel<<<BN_TOK, 256>>>(ps, enc, nullptr, ca_g, ca_b, psa);

    // ---- FeedForward ----
    GEMM_GE<<<dim3(32,32,1), 256, S_NN>>>(psa, w1, pff, b1, Dd, Dd, MLPd, MLPd, 1, 0,0,0,0,0,0, 1.0f);
    GEMM_NN<<<dim3(8,32,1), 256, S_NN>>>(pff, w2, pt, nullptr, MLPd, MLPd, Dd, Dd, 1, 0,0,0,0,0,0, 1.0f);
    add_ln_kernel<<<BN_TOK, 256>>>(pt, psa, b2, ff_g, ff_b, out);
}

// round 6
// speedup vs baseline: 5.2816x; 1.0880x over previous
#include <cuda_runtime.h>
#include <math.h>
#include <stdint.h>

// ---------------- problem constants ----------------
#define Bb   4
#define Nn   1024
#define Dd   1024
#define Hh   16
#define DH   64
#define MLPd 4096

#define BN_TOK (Bb*Nn)        // 4096 rows
#define MAT    (Bb*Nn*Dd)     // 4M elems, 16MB

// ---------------- device scratch ----------------
__device__ float g_q [MAT];                 // q / qc
__device__ float g_k [MAT];                 // k / kc
__device__ float g_v [MAT];                 // v / vc
__device__ float g_s [MAT];                 // sa dots+attn / ca flash out
__device__ float g_sa[MAT];                 // sa (post-LN) / ca (post-LN)
__device__ float g_t [MAT];                 // T_full / h2
__device__ float g_ff[(long)BN_TOK*MLPd];   // FF hidden (64MB)
// pre-rounded (tf32) copies of external inputs
__device__ float g_xr [MAT];
__device__ float g_er [MAT];
__device__ float g_wsq[Dd*Dd];
__device__ float g_wsk[Dd*Dd];
__device__ float g_wsv[Dd*Dd];
__device__ float g_wcq[Dd*Dd];
__device__ float g_wck[Dd*Dd];
__device__ float g_wcv[Dd*Dd];
__device__ float g_w1r[Dd*MLPd];
__device__ float g_w2r[MLPd*Dd];

// ---------------- helpers ----------------
__device__ __forceinline__ uint32_t smem_u32(const void* p) {
    uint32_t a;
    asm("{ .reg .u64 t; cvta.to.shared.u64 t, %1; cvt.u32.u64 %0, t; }" : "=r"(a) : "l"(p));
    return a;
}
#define CP_ASYNC16(dst, src) \
    asm volatile("cp.async.cg.shared.global [%0], [%1], 16;" :: "r"(dst), "l"(src) : "memory")
#define CP_COMMIT() asm volatile("cp.async.commit_group;" ::: "memory")
#define CP_WAIT(n)  asm volatile("cp.async.wait_group %0;" :: "n"(n) : "memory")

__device__ __forceinline__ uint32_t to_tf32(float f) {
    uint32_t u;
    asm("cvt.rna.tf32.f32 %0, %1;" : "=r"(u) : "f"(f));
    return u;
}
__device__ __forceinline__ float round_tf32f(float f) { return __uint_as_float(to_tf32(f)); }

__device__ __forceinline__ void mma_tf32(float* d, const uint32_t* a, const uint32_t* b) {
    asm volatile(
        "mma.sync.aligned.m16n8k8.row.col.f32.tf32.tf32.f32 "
        "{%0,%1,%2,%3}, {%4,%5,%6,%7}, {%8,%9}, {%0,%1,%2,%3};"
        : "+f"(d[0]), "+f"(d[1]), "+f"(d[2]), "+f"(d[3])
        : "r"(a[0]), "r"(a[1]), "r"(a[2]), "r"(a[3]), "r"(b[0]), "r"(b[1]));
}
__device__ __forceinline__ float gelu_exact(float x) {
    return 0.5f * x * (1.0f + erff(x * 0.70710678118654752f));
}

// ================= one-shot tf32 rounding of external inputs =================
#define NROUND 10
struct RoundArgs {
    const float* src[NROUND];
    float*       dst[NROUND];
    int          n4 [NROUND];   // element count / 4
};
__global__ void __launch_bounds__(256)
round_tf32_kernel(RoundArgs a)
{
    const int which = blockIdx.y;
    const int t = blockIdx.x * 256 + threadIdx.x;
    if (t >= a.n4[which]) return;
    const float4 v = reinterpret_cast<const float4*>(a.src[which])[t];
    float4 o;
    o.x = round_tf32f(v.x); o.y = round_tf32f(v.y);
    o.z = round_tf32f(v.z); o.w = round_tf32f(v.w);
    reinterpret_cast<float4*>(a.dst[which])[t] = o;
}

// ================= tf32 mma.sync GEMM (3-stage pipeline, no in-loop cvt) =================
// Inputs A and B MUST be pre-rounded to tf32 bit patterns.
// TRB=false: C = alpha*A@B,   A:[M,K] lda, B:[K,N] ldb (row-major)
// TRB=true : C = alpha*A@B^T, A:[M,K] lda, B:[N,K] ldb (row-major)
// GELU=true: C = gelu(A@B + bias[col])
// rnd!=0: round C to tf32 (for outputs consumed by later GEMMs).
template<bool TRB, bool GELU>
__global__ void __launch_bounds__(256, 2)
gemm_mma(const float* __restrict__ A, const float* __restrict__ B, float* __restrict__ C,
         const float* __restrict__ bias,
         int K, int lda, int ldb, int ldc, int bdiv,
         long sAb, long sAh, long sBb, long sBh, long sCb, long sCh, float alpha, int rnd)
{
    constexpr int BM  = 128, BN = 128, BK = 32;
    constexpr int SA  = BK + 4;                    // A smem row stride (36)
    constexpr int SBN = TRB ? (BK + 4) : (BN + 8); // B smem row stride
    constexpr int ASZ = BM * SA;
    constexpr int BSZ = TRB ? (BN * SBN) : (BK * SBN);

    extern __shared__ float sm[];
    float* As = sm;
    float* Bs = sm + 3 * ASZ;
    const uint32_t sAs = smem_u32(As), sBs = smem_u32(Bs);

    const int z = blockIdx.z, zb = z / bdiv, zh = z % bdiv;
    A += zb * sAb + zh * sAh;
    B += zb * sBb + zh * sBh;
    C += zb * sCb + zh * sCh;

    const int tid  = threadIdx.x;
    const int wid  = tid >> 5, lane = tid & 31;
    const int g    = lane >> 2, tig = lane & 3;
    const int m0   = (wid >> 2) * 64;
    const int n0   = (wid & 3) * 32;
    const int rowBase = blockIdx.y * BM;
    const int colBase = blockIdx.x * BN;

    float acc[4][4][4];
    #pragma unroll
    for (int mt = 0; mt < 4; mt++)
        #pragma unroll
        for (int nt = 0; nt < 4; nt++)
            #pragma unroll
            for (int i = 0; i < 4; i++) acc[mt][nt][i] = 0.0f;

    const int nC = K >> 5;

    auto stage_copy = [&](int s, int k0) {
        #pragma unroll
        for (int j = 0; j < 4; j++) {
            const int cid = tid + j * 256;
            const int r = cid >> 3, c16 = cid & 7;
            CP_ASYNC16(sAs + (uint32_t)((s * ASZ + r * SA + c16 * 4) * 4),
                       A + (long)(rowBase + r) * lda + k0 + c16 * 4);
        }
        if (TRB) {
            #pragma unroll
            for (int j = 0; j < 4; j++) {
                const int cid = tid + j * 256;
                const int r = cid >> 3, c16 = cid & 7;
                CP_ASYNC16(sBs + (uint32_t)((s * BSZ + r * SBN + c16 * 4) * 4),
                           B + (long)(colBase + r) * ldb + k0 + c16 * 4);
            }
        } else {
            #pragma unroll
            for (int j = 0; j < 4; j++) {
                const int cid = tid + j * 256;
                const int r = cid >> 5, c16 = cid & 31;
                CP_ASYNC16(sBs + (uint32_t)((s * BSZ + r * SBN + c16 * 4) * 4),
                           B + (long)(k0 + r) * ldb + colBase + c16 * 4);
            }
        }
    };

    auto compute = [&](int s) {
        const uint32_t* ab = reinterpret_cast<const uint32_t*>(As + s * ASZ);
        const uint32_t* bb = reinterpret_cast<const uint32_t*>(Bs + s * BSZ);
        #pragma unroll
        for (int kk = 0; kk < 4; kk++) {
            const int kb = kk * 8;
            uint32_t af[4][4], bf[4][2];
            #pragma unroll
            for (int mt = 0; mt < 4; mt++) {
                const int r0 = m0 + mt * 16 + g;
                af[mt][0] = ab[r0 * SA + kb + tig];
                af[mt][1] = ab[(r0 + 8) * SA + kb + tig];
                af[mt][2] = ab[r0 * SA + kb + tig + 4];
                af[mt][3] = ab[(r0 + 8) * SA + kb + tig + 4];
            }
            #pragma unroll
            for (int nt = 0; nt < 4; nt++) {
                const int cc = n0 + nt * 8 + g;
                if (TRB) {
                    bf[nt][0] = bb[cc * SBN + kb + tig];
                    bf[nt][1] = bb[cc * SBN + kb + tig + 4];
                } else {
                    bf[nt][0] = bb[(kb + tig) * SBN + cc];
                    bf[nt][1] = bb[(kb + tig + 4) * SBN + cc];
                }
            }
            #pragma unroll
            for (int mt = 0; mt < 4; mt++)
                #pragma unroll
                for (int nt = 0; nt < 4; nt++)
                    mma_tf32(acc[mt][nt], af[mt], bf[nt]);
        }
    };

    stage_copy(0, 0); CP_COMMIT();
    stage_copy(1, BK); CP_COMMIT();
    for (int c = 0; c < nC; c++) {
        if (c + 1 < nC) { CP_WAIT(1); } else { CP_WAIT(0); }
        __syncthreads();
        compute(c % 3);
        if (c + 2 < nC) { stage_copy((c + 2) % 3, (c + 2) * BK); CP_COMMIT(); }
    }

    // epilogue
    #pragma unroll
    for (int mt = 0; mt < 4; mt++) {
        const int r0 = rowBase + m0 + mt * 16 + g;
        #pragma unroll
        for (int nt = 0; nt < 4; nt++) {
            const int cc = colBase + n0 + nt * 8 + 2 * tig;
            float v0 = acc[mt][nt][0], v1 = acc[mt][nt][1];
            float v2 = acc[mt][nt][2], v3 = acc[mt][nt][3];
            if (GELU) {
                const float b0 = bias[cc], b1 = bias[cc + 1];
                v0 = gelu_exact(v0 + b0); v1 = gelu_exact(v1 + b1);
                v2 = gelu_exact(v2 + b0); v3 = gelu_exact(v3 + b1);
            } else {
                v0 *= alpha; v1 *= alpha; v2 *= alpha; v3 *= alpha;
            }
            if (rnd) {
                v0 = round_tf32f(v0); v1 = round_tf32f(v1);
                v2 = round_tf32f(v2); v3 = round_tf32f(v3);
            }
            *reinterpret_cast<float2*>(C + (long)r0 * ldc + cc)       = make_float2(v0, v1);
            *reinterpret_cast<float2*>(C + (long)(r0 + 8) * ldc + cc) = make_float2(v2, v3);
        }
    }
}

// ================= fused CA flash attention =================
// Inputs T (Q), KC, VC pre-rounded to tf32. Per CTA: 128 query rows x one head.
// S = (T_h @ kc_h^T)/64, P = exp(S) rounded, O = (P @ vc_h) / rowsum(P).
#define FQ_OFF 0
#define FK_OFF 8704
#define FP_OFF 17408
#define FV_OFF 34304
#define FLASH_SMEM ((34304 + 64*132) * 4)   // 171008 B

__global__ void __launch_bounds__(256)
flash_ca(const float* __restrict__ T, const float* __restrict__ KC,
         const float* __restrict__ VC, float* __restrict__ O)
{
    extern __shared__ float sm[];
    float* Qs = sm + FQ_OFF;   // [128][68]
    float* Ks = sm + FK_OFF;   // [128][68]
    float* Ps = sm + FP_OFF;   // [128][132]
    float* Vt = sm + FV_OFF;   // [64][132]  (V^T)
    const uint32_t sQ = smem_u32(Qs), sK = smem_u32(Ks);
    const uint32_t* Qs32 = reinterpret_cast<const uint32_t*>(Qs);
    const uint32_t* Ks32 = reinterpret_cast<const uint32_t*>(Ks);
    const uint32_t* Ps32 = reinterpret_cast<const uint32_t*>(Ps);
    const uint32_t* Vt32 = reinterpret_cast<const uint32_t*>(Vt);

    const int b = blockIdx.z, h = blockIdx.y;
    const int rowBase = blockIdx.x * 128;
    const float* Tb = T  + ((long)b * Nn + rowBase) * Dd + h * DH;
    const float* Kb = KC + (long)b * Nn * Dd + h * DH;
    const float* Vb = VC + (long)b * Nn * Dd + h * DH;
    float* Ob       = O  + ((long)b * Nn + rowBase) * Dd + h * DH;

    const int tid = threadIdx.x;
    const int wid = tid >> 5, lane = tid & 31;
    const int g = lane >> 2, tig = lane & 3;
    const int m0  = (wid >> 2) * 64;
    const int n0  = (wid & 3) * 32;   // S-phase cols
    const int n0v = (wid & 3) * 16;   // PV-phase cols

    float accO[4][2][4];
    float den[4][2];
    #pragma unroll
    for (int mt = 0; mt < 4; mt++) {
        den[mt][0] = den[mt][1] = 0.0f;
        #pragma unroll
        for (int nt = 0; nt < 2; nt++)
            #pragma unroll
            for (int i = 0; i < 4; i++) accO[mt][nt][i] = 0.0f;
    }

    // prologue: Q tile (once) + K tile 0. 128 rows x 16 f4-chunks = 2048 chunks.
    #pragma unroll
    for (int j = 0; j < 8; j++) {
        const int cid = tid + j * 256;
        const int r = cid >> 4, c16 = cid & 15;
        CP_ASYNC16(sQ + (uint32_t)((r * 68 + c16 * 4) * 4), Tb + (long)r * Dd + c16 * 4);
        CP_ASYNC16(sK + (uint32_t)((r * 68 + c16 * 4) * 4), Kb + (long)r * Dd + c16 * 4);
    }
    CP_COMMIT();

    const int jrow = tid >> 1;            // V^T loader: key row
    const int dhalf = (tid & 1) * 32;     // d half

    for (int jt = 0; jt < 8; jt++) {
        if (jt > 0) {
            #pragma unroll
            for (int j = 0; j < 8; j++) {
                const int cid = tid + j * 256;
                const int r = cid >> 4, c16 = cid & 15;
                CP_ASYNC16(sK + (uint32_t)((r * 68 + c16 * 4) * 4),
                           Kb + (long)(jt * 128 + r) * Dd + c16 * 4);
            }
            CP_COMMIT();
        }
        // V tile into regs (already tf32-rounded in gmem)
        float4 vreg[8];
        #pragma unroll
        for (int i = 0; i < 8; i++)
            vreg[i] = *reinterpret_cast<const float4*>(Vb + (long)(jt * 128 + jrow) * Dd + dhalf + i * 4);

        CP_WAIT(0);
        __syncthreads();

        // V^T store
        #pragma unroll
        for (int i = 0; i < 8; i++) {
            const int d = dhalf + i * 4;
            Vt[(d + 0) * 132 + jrow] = vreg[i].x;
            Vt[(d + 1) * 132 + jrow] = vreg[i].y;
            Vt[(d + 2) * 132 + jrow] = vreg[i].z;
            Vt[(d + 3) * 132 + jrow] = vreg[i].w;
        }

        // S = Q @ K^T (K-dim 64)
        float accS[4][4][4];
        #pragma unroll
        for (int mt = 0; mt < 4; mt++)
            #pragma unroll
            for (int nt = 0; nt < 4; nt++)
                #pragma unroll
                for (int i = 0; i < 4; i++) accS[mt][nt][i] = 0.0f;
        #pragma unroll
        for (int kk = 0; kk < 8; kk++) {
            const int kb = kk * 8;
            uint32_t af[4][4], bf[4][2];
            #pragma unroll
            for (int mt = 0; mt < 4; mt++) {
                const int r0 = m0 + mt * 16 + g;
                af[mt][0] = Qs32[r0 * 68 + kb + tig];
                af[mt][1] = Qs32[(r0 + 8) * 68 + kb + tig];
                af[mt][2] = Qs32[r0 * 68 + kb + tig + 4];
                af[mt][3] = Qs32[(r0 + 8) * 68 + kb + tig + 4];
            }
            #pragma unroll
            for (int nt = 0; nt < 4; nt++) {
                const int cc = n0 + nt * 8 + g;
                bf[nt][0] = Ks32[cc * 68 + kb + tig];
                bf[nt][1] = Ks32[cc * 68 + kb + tig + 4];
            }
            #pragma unroll
            for (int mt = 0; mt < 4; mt++)
                #pragma unroll
                for (int nt = 0; nt < 4; nt++)
                    mma_tf32(accS[mt][nt], af[mt], bf[nt]);
        }

        // exp (tf32-rounded), denominator partials, P store
        #pragma unroll
        for (int mt = 0; mt < 4; mt++) {
            const int r0 = m0 + mt * 16 + g;
            #pragma unroll
            for (int nt = 0; nt < 4; nt++) {
                const int col = n0 + nt * 8 + 2 * tig;
                const float e0 = round_tf32f(expf(accS[mt][nt][0] * 0.015625f));
                const float e1 = round_tf32f(expf(accS[mt][nt][1] * 0.015625f));
                const float e2 = round_tf32f(expf(accS[mt][nt][2] * 0.015625f));
                const float e3 = round_tf32f(expf(accS[mt][nt][3] * 0.015625f));
                den[mt][0] += e0 + e1;
                den[mt][1] += e2 + e3;
                *reinterpret_cast<float2*>(&Ps[r0 * 132 + col])       = make_float2(e0, e1);
                *reinterpret_cast<float2*>(&Ps[(r0 + 8) * 132 + col]) = make_float2(e2, e3);
            }
        }
        __syncthreads();   // P + V^T visible

        // O += P @ V   (K-dim 128)
        #pragma unroll
        for (int kk = 0; kk < 16; kk++) {
            const int kb = kk * 8;
            uint32_t af[4][4], bf[2][2];
            #pragma unroll
            for (int mt = 0; mt < 4; mt++) {
                const int r0 = m0 + mt * 16 + g;
                af[mt][0] = Ps32[r0 * 132 + kb + tig];
                af[mt][1] = Ps32[(r0 + 8) * 132 + kb + tig];
                af[mt][2] = Ps32[r0 * 132 + kb + tig + 4];
                af[mt][3] = Ps32[(r0 + 8) * 132 + kb + tig + 4];
            }
            #pragma unroll
            for (int nt = 0; nt < 2; nt++) {
                const int dc = n0v + nt * 8 + g;
                bf[nt][0] = Vt32[dc * 132 + kb + tig];
                bf[nt][1] = Vt32[dc * 132 + kb + tig + 4];
            }
            #pragma unroll
            for (int mt = 0; mt < 4; mt++)
                #pragma unroll
                for (int nt = 0; nt < 2; nt++)
                    mma_tf32(accO[mt][nt], af[mt], bf[nt]);
        }
        __syncthreads();   // protect Ks/Vt/Ps for next tile
    }

    // denominator: reduce over tig lanes, then across 4 column-warps via smem
    float* Dred = Ps;   // reuse [128][4]
    const int nc = wid & 3;
    #pragma unroll
    for (int mt = 0; mt < 4; mt++) {
        float d0 = den[mt][0], d1 = den[mt][1];
        d0 += __shfl_xor_sync(0xffffffffu, d0, 1); d0 += __shfl_xor_sync(0xffffffffu, d0, 2);
        d1 += __shfl_xor_sync(0xffffffffu, d1, 1); d1 += __shfl_xor_sync(0xffffffffu, d1, 2);
        if (tig == 0) {
            Dred[(m0 + mt * 16 + g) * 4 + nc]     = d0;
            Dred[(m0 + mt * 16 + g + 8) * 4 + nc] = d1;
        }
    }
    __syncthreads();

    #pragma unroll
    for (int mt = 0; mt < 4; mt++) {
        const int r0 = m0 + mt * 16 + g;
        const float4 q0 = *reinterpret_cast<const float4*>(&Dred[r0 * 4]);
        const float4 q1 = *reinterpret_cast<const float4*>(&Dred[(r0 + 8) * 4]);
        const float inv0 = 1.0f / (q0.x + q0.y + q0.z + q0.w);
        const float inv1 = 1.0f / (q1.x + q1.y + q1.z + q1.w);
        #pragma unroll
        for (int nt = 0; nt < 2; nt++) {
            const int col = n0v + nt * 8 + 2 * tig;
            *reinterpret_cast<float2*>(Ob + (long)r0 * Dd + col) =
                make_float2(accO[mt][nt][0] * inv0, accO[mt][nt][1] * inv0);
            *reinterpret_cast<float2*>(Ob + (long)(r0 + 8) * Dd + col) =
                make_float2(accO[mt][nt][2] * inv1, accO[mt][nt][3] * inv1);
        }
    }
}

// ================= row softmax (row length 1024, 256 threads, tf32-rounded out) ==========
__global__ void softmax_kernel(float* __restrict__ X)
{
    long off = (long)blockIdx.x * 1024;
    int tid = threadIdx.x;
    float xv[4];
    float m = -INFINITY;
    #pragma unroll
    for (int i = 0; i < 4; i++) { xv[i] = X[off + tid + i*256]; m = fmaxf(m, xv[i]); }

    __shared__ float red[32];
    #pragma unroll
    for (int o = 16; o; o >>= 1) m = fmaxf(m, __shfl_xor_sync(0xffffffffu, m, o));
    if ((tid & 31) == 0) red[tid >> 5] = m;
    __syncthreads();
    if (tid < 32) {
        float v = (tid < 8) ? red[tid] : -INFINITY;
        #pragma unroll
        for (int o = 16; o; o >>= 1) v = fmaxf(v, __shfl_xor_sync(0xffffffffu, v, o));
        if (tid == 0) red[0] = v;
    }
    __syncthreads();
    m = red[0];

    float s = 0.0f;
    #pragma unroll
    for (int i = 0; i < 4; i++) { xv[i] = expf(xv[i] - m); s += xv[i]; }
    __syncthreads();
    #pragma unroll
    for (int o = 16; o; o >>= 1) s += __shfl_xor_sync(0xffffffffu, s, o);
    if ((tid & 31) == 0) red[tid >> 5] = s;
    __syncthreads();
    if (tid < 32) {
        float v = (tid < 8) ? red[tid] : 0.0f;
        #pragma unroll
        for (int o = 16; o; o >>= 1) v += __shfl_xor_sync(0xffffffffu, v, o);
        if (tid == 0) red[0] = v;
    }
    __syncthreads();
    float inv = 1.0f / red[0];
    #pragma unroll
    for (int i = 0; i < 4; i++) X[off + tid + i*256] = round_tf32f(xv[i] * inv);
}

// ================= out = LN(A + R (+ bias)) * gamma + beta, optional tf32 round ==========
__global__ void add_ln_kernel(const float* __restrict__ A, const float* __restrict__ R,
                              const float* __restrict__ bias,
                              const float* __restrict__ gamma, const float* __restrict__ beta,
                              float* __restrict__ out, int rnd)
{
    long off = (long)blockIdx.x * 1024;
    int tid = threadIdx.x;
    float xv[4];
    float s = 0.0f, s2 = 0.0f;
    #pragma unroll
    for (int i = 0; i < 4; i++) {
        int c = tid + i*256;
        float v = A[off + c] + R[off + c];
        if (bias) v += bias[c];
        xv[i] = v; s += v; s2 += v*v;
    }
    __shared__ float rs[32], rs2[32];
    #pragma unroll
    for (int o = 16; o; o >>= 1) { s += __shfl_xor_sync(0xffffffffu, s, o); s2 += __shfl_xor_sync(0xffffffffu, s2, o); }
    if ((tid & 31) == 0) { rs[tid >> 5] = s; rs2[tid >> 5] = s2; }
    __syncthreads();
    if (tid < 32) {
        float a = (tid < 8) ? rs[tid]  : 0.0f;
        float b = (tid < 8) ? rs2[tid] : 0.0f;
        #pragma unroll
        for (int o = 16; o; o >>= 1) { a += __shfl_xor_sync(0xffffffffu, a, o); b += __shfl_xor_sync(0xffffffffu, b, o); }
        if (tid == 0) { rs[0] = a; rs2[0] = b; }
    }
    __syncthreads();
    float mu  = rs[0]  * (1.0f / 1024.0f);
    float var = rs2[0] * (1.0f / 1024.0f) - mu * mu;
    float inv = rsqrtf(var + 1e-5f);
    #pragma unroll
    for (int i = 0; i < 4; i++) {
        int c = tid + i*256;
        float v = (xv[i] - mu) * inv * gamma[c] + beta[c];
        out[off + c] = rnd ? round_tf32f(v) : v;
    }
}

// ================= launch =================
extern "C" void kernel_launch(void* const* d_in, const int* in_sizes, int n_in,
                              void* d_out, int out_size)
{
    const float* x      = (const float*)d_in[0];
    const float* enc    = (const float*)d_in[1];
    const float* sa_wq  = (const float*)d_in[2];
    const float* sa_wk  = (const float*)d_in[3];
    const float* sa_wv  = (const float*)d_in[4];
    const float* sa_g   = (const float*)d_in[5];
    const float* sa_b   = (const float*)d_in[6];
    const float* ca_wq  = (const float*)d_in[7];
    const float* ca_wk  = (const float*)d_in[8];
    const float* ca_wv  = (const float*)d_in[9];
    const float* ca_g   = (const float*)d_in[10];
    const float* ca_b   = (const float*)d_in[11];
    const float* w1     = (const float*)d_in[12];
    const float* b1     = (const float*)d_in[13];
    const float* w2     = (const float*)d_in[14];
    const float* b2     = (const float*)d_in[15];
    const float* ff_g   = (const float*)d_in[16];
    const float* ff_b   = (const float*)d_in[17];
    float* out = (float*)d_out;

    float *pq, *pk, *pv, *ps, *psa, *pt, *pff;
    float *pxr, *per, *pwsq, *pwsk, *pwsv, *pwcq, *pwck, *pwcv, *pw1, *pw2;
    cudaGetSymbolAddress((void**)&pq,  g_q);
    cudaGetSymbolAddress((void**)&pk,  g_k);
    cudaGetSymbolAddress((void**)&pv,  g_v);
    cudaGetSymbolAddress((void**)&ps,  g_s);
    cudaGetSymbolAddress((void**)&psa, g_sa);
    cudaGetSymbolAddress((void**)&pt,  g_t);
    cudaGetSymbolAddress((void**)&pff, g_ff);
    cudaGetSymbolAddress((void**)&pxr,  g_xr);
    cudaGetSymbolAddress((void**)&per,  g_er);
    cudaGetSymbolAddress((void**)&pwsq, g_wsq);
    cudaGetSymbolAddress((void**)&pwsk, g_wsk);
    cudaGetSymbolAddress((void**)&pwsv, g_wsv);
    cudaGetSymbolAddress((void**)&pwcq, g_wcq);
    cudaGetSymbolAddress((void**)&pwck, g_wck);
    cudaGetSymbolAddress((void**)&pwcv, g_wcv);
    cudaGetSymbolAddress((void**)&pw1,  g_w1r);
    cudaGetSymbolAddress((void**)&pw2,  g_w2r);

    const long MM = (long)Nn * Dd;

    constexpr int S_NN = (3 * 128 * 36 + 3 * 32 * 136) * 4;  // 107520 B
    constexpr int S_NT = (3 * 128 * 36 + 3 * 128 * 36) * 4;  // 110592 B
    cudaFuncSetAttribute((const void*)gemm_mma<false,false>, cudaFuncAttributeMaxDynamicSharedMemorySize, S_NN);
    cudaFuncSetAttribute((const void*)gemm_mma<false,true>,  cudaFuncAttributeMaxDynamicSharedMemorySize, S_NN);
    cudaFuncSetAttribute((const void*)gemm_mma<true,false>,  cudaFuncAttributeMaxDynamicSharedMemorySize, S_NT);
    cudaFuncSetAttribute((const void*)flash_ca, cudaFuncAttributeMaxDynamicSharedMemorySize, FLASH_SMEM);
    cudaFuncSetAttribute((const void*)gemm_mma<false,false>, cudaFuncAttributePreferredSharedMemoryCarveout, 100);
    cudaFuncSetAttribute((const void*)gemm_mma<false,true>,  cudaFuncAttributePreferredSharedMemoryCarveout, 100);
    cudaFuncSetAttribute((const void*)gemm_mma<true,false>,  cudaFuncAttributePreferredSharedMemoryCarveout, 100);

    // ---- pre-round external inputs to tf32 ----
    RoundArgs ra;
    ra.src[0] = x;     ra.dst[0] = pxr;  ra.n4[0] = MAT / 4;
    ra.src[1] = enc;   ra.dst[1] = per;  ra.n4[1] = MAT / 4;
    ra.src[2] = sa_wq; ra.dst[2] = pwsq; ra.n4[2] = Dd * Dd / 4;
    ra.src[3] = sa_wk; ra.dst[3] = pwsk; ra.n4[3] = Dd * Dd / 4;
    ra.src[4] = sa_wv; ra.dst[4] = pwsv; ra.n4[4] = Dd * Dd / 4;
    ra.src[5] = ca_wq; ra.dst[5] = pwcq; ra.n4[5] = Dd * Dd / 4;
    ra.src[6] = ca_wk; ra.dst[6] = pwck; ra.n4[6] = Dd * Dd / 4;
    ra.src[7] = ca_wv; ra.dst[7] = pwcv; ra.n4[7] = Dd * Dd / 4;
    ra.src[8] = w1;    ra.dst[8] = pw1;  ra.n4[8] = Dd * MLPd / 4;
    ra.src[9] = w2;    ra.dst[9] = pw2;  ra.n4[9] = MLPd * Dd / 4;
    round_tf32_kernel<<<dim3(MAT / 4 / 256, NROUND, 1), 256>>>(ra);

    #define GEMM_NN gemm_mma<false,false>
    #define GEMM_NT gemm_mma<true,false>
    #define GEMM_GE gemm_mma<false,true>

    // ---- Self attention ----
    GEMM_NN<<<dim3(8,32,1), 256, S_NN>>>(pxr, pwsq, pq, nullptr, Dd, Dd, Dd, Dd, 1, 0,0,0,0,0,0, 1.0f, 1);
    GEMM_NN<<<dim3(8,32,1), 256, S_NN>>>(pxr, pwsk, pk, nullptr, Dd, Dd, Dd, Dd, 1, 0,0,0,0,0,0, 1.0f, 1);
    GEMM_NN<<<dim3(8,32,1), 256, S_NN>>>(pxr, pwsv, pv, nullptr, Dd, Dd, Dd, Dd, 1, 0,0,0,0,0,0, 1.0f, 1);
    // dots = (1/32) q @ k^T   (NT)
    GEMM_NT<<<dim3(8,8,Bb), 256, S_NT>>>(pq, pk, ps, nullptr, Dd, Dd, Dd, Nn, 1, MM,0, MM,0, MM,0, 0.03125f, 0);
    softmax_kernel<<<Bb*Nn, 256>>>(ps);
    GEMM_NN<<<dim3(8,8,Bb), 256, S_NN>>>(ps, pv, psa, nullptr, Nn, Nn, Dd, Dd, 1, MM,0, MM,0, MM,0, 1.0f, 0);
    add_ln_kernel<<<BN_TOK, 256>>>(psa, x, nullptr, sa_g, sa_b, psa, 1);

    // ---- Cross attention (kkt folded; softmax/PV fused flash) ----
    GEMM_NN<<<dim3(8,32,1), 256, S_NN>>>(psa, pwcq, pq, nullptr, Dd, Dd, Dd, Dd, 1, 0,0,0,0,0,0, 1.0f, 1); // qc
    GEMM_NN<<<dim3(8,32,1), 256, S_NN>>>(per, pwck, pk, nullptr, Dd, Dd, Dd, Dd, 1, 0,0,0,0,0,0, 1.0f, 1); // kc
    GEMM_NN<<<dim3(8,32,1), 256, S_NN>>>(per, pwcv, pv, nullptr, Dd, Dd, Dd, Dd, 1, 0,0,0,0,0,0, 1.0f, 1); // vc
    // T_full = qc @ kc (NN, per batch)
    GEMM_NN<<<dim3(8,8,Bb), 256, S_NN>>>(pq, pk, pt, nullptr, Dd, Dd, Dd, Dd, 1, MM,0, MM,0, MM,0, 1.0f, 1);
    // fused: S = T_h @ kc_h^T / 64, softmax, @ vc_h
    flash_ca<<<dim3(8,16,4), 256, FLASH_SMEM>>>(pt, pk, pv, ps);
    add_ln_kernel<<<BN_TOK, 256>>>(ps, enc, nullptr, ca_g, ca_b, psa, 1);

    // ---- FeedForward ----
    GEMM_GE<<<dim3(32,32,1), 256, S_NN>>>(psa, pw1, pff, b1, Dd, Dd, MLPd, MLPd, 1, 0,0,0,0,0,0, 1.0f, 1);
    GEMM_NN<<<dim3(8,32,1), 256, S_NN>>>(pff, pw2, pt, nullptr, MLPd, MLPd, Dd, Dd, 1, 0,0,0,0,0,0, 1.0f, 0);
    add_ln_kernel<<<BN_TOK, 256>>>(pt, psa, b2, ff_g, ff_b, out, 0);
}